// round 5
// baseline (speedup 1.0000x reference)
#include <cuda_runtime.h>

// LQR via Riccati recursion. T=128, n_state=16, n_ctrl=8, n_all=24.
// Single CTA, 160 threads. Stage structure (4 barriers):
//   P1: Qu rows (Quu,Qux,qu) by ALL threads (small f2 tasks)  -> barrier
//   P2: warp0 lanes 0-16: fused Cholesky+solves (register-resident)
//       || warps 1-4: Qxx rows, qx, c/C prefetches             -> barrier
//   P3: P, p, Acl, bias                                        -> barrier
//   P4: W = P*F                                                -> barrier

constexpr int TT = 128, NS = 16, NC = 8, NA = 24;
constexpr int NTHR = 160;

constexpr int QS = 28;  // sQ row stride (floats)
constexpr int WS = 28;  // sW row stride
constexpr int PS = 20;  // sP row stride
constexpr int AS = 17;  // Acl row stride

__device__ __align__(16) float g_K[TT][NC][NS];
__device__ float g_kk[TT][NC];
__device__ __align__(16) float g_P[TT][NS][NS];
__device__ float g_p[TT][NS];

__global__ void __launch_bounds__(NTHR, 1) lqr_kernel(
    const float* __restrict__ A, const float* __restrict__ B,
    const float* __restrict__ x0, const float* __restrict__ C,
    const float* __restrict__ c, float* __restrict__ out)
{
    extern __shared__ float sAcl[];            // [TT][NS][AS]
    __shared__ __align__(16) float sF[NS][NA]; // [A B]
    __shared__ __align__(16) float sW[NS][WS];
    __shared__ __align__(16) float sQ[NA][QS];
    __shared__ __align__(16) float sP[NS][PS];
    __shared__ __align__(16) float sK[NC][NS];
    __shared__ float sq[NA], sp[NS], skk[NC];
    __shared__ __align__(16) float scq[2][NA]; // double-buffered c_t staging
    __shared__ float sBias[TT][NS];
    __shared__ float sX[TT][NS];

    const int tid = threadIdx.x;

    for (int idx = tid; idx < NS * NA; idx += NTHR) {
        int i = idx / NA, j = idx % NA;
        sF[i][j] = (j < NS) ? A[i * NS + j] : B[i * NC + (j - NS)];
    }
    if (tid < NA) scq[(TT - 1) & 1][tid] = c[(TT - 1) * NA + tid];
    __syncthreads();

    const float2* C2 = (const float2*)C;   // stage stride 288 float2
    const float4* C4 = (const float4*)C;   // stage stride 144 float4

    // Roles:
    //  P1: tid<96:  Qu f2 task: m=tid/12, jh=tid%12. tid 96..103: qu (m=tid-96).
    //  P2: tid<=16: CD. tid 32..127: Qxx f4 (i=(tid-32)/6, jq=(tid-32)%6).
    //      tid 128..143: qx (i=tid-128). tid 144..149: c-prefetch.
    const int bm  = tid / 12, bjh = tid % 12;        // P1 mapping (tid<96)
    const int xi  = (tid - 32) / 6, xjq = (tid - 32) % 6; // P2 Qxx (32<=tid<128)

    float2 cregU = make_float2(0.f, 0.f);
    float4 cregA = make_float4(0.f, 0.f, 0.f, 0.f);
    if (tid < 96)
        cregU = C2[(TT - 1) * 288 + (NS + bm) * 12 + bjh];
    if (tid >= 32 && tid < 128)
        cregA = C4[(TT - 1) * 144 + xi * 6 + xjq];

    // ---------------- Backward Riccati pass ----------------
#pragma unroll 1
    for (int t = TT - 1; t >= 0; --t) {
        const int par = t & 1;
        const bool notlast = (t != TT - 1);

        // ---- P1: Qu rows + qu (everyone) ----
        if (tid < 96) {
            float2 s = cregU;
            if (notlast) {
#pragma unroll
                for (int k = 0; k < NS; ++k) {
                    float f = sF[k][NS + bm];               // broadcast LDS
                    float2 w = *(const float2*)&sW[k][2 * bjh];
                    s.x = fmaf(f, w.x, s.x); s.y = fmaf(f, w.y, s.y);
                }
            }
            *(float2*)&sQ[NS + bm][2 * bjh] = s;
            if (t > 0) cregU = C2[(t - 1) * 288 + (NS + bm) * 12 + bjh];
        } else if (tid < 104) {
            int m = tid - 96;
            float s = scq[par][NS + m];
            if (notlast) {
#pragma unroll
                for (int k = 0; k < NS; ++k) s = fmaf(sF[k][NS + m], sp[k], s);
            }
            sq[NS + m] = s;
        }
        __syncthreads();

        // ---- P2: CD (warp0) || Qxx, qx, prefetch (warps 1-4) ----
        if (tid < 32) {
            if (tid <= NS) {
                // Preload Quu lower triangle + RHS into registers
                float Lm[NC][NC];
#pragma unroll
                for (int j = 0; j < NC; ++j)
#pragma unroll
                    for (int i = 0; i < NC; ++i)
                        if (i >= j) Lm[i][j] = sQ[NS + i][NS + j];
                float y[NC];
#pragma unroll
                for (int a = 0; a < NC; ++a)
                    y[a] = (tid < NS) ? sQ[NS + a][tid] : sq[NS + a];
                float invd[NC];
                // Right-looking scaled Cholesky with fused forward solve
#pragma unroll
                for (int j = 0; j < NC; ++j) {
                    float r = rsqrtf(Lm[j][j]);
                    invd[j] = r;
                    y[j] *= r;
#pragma unroll
                    for (int i = j + 1; i < NC; ++i) Lm[i][j] *= r;
#pragma unroll
                    for (int i = j + 1; i < NC; ++i) {
                        y[i] = fmaf(-Lm[i][j], y[j], y[i]);
#pragma unroll
                        for (int l = j + 1; l <= i; ++l)
                            Lm[i][l] = fmaf(-Lm[i][j], Lm[l][j], Lm[i][l]);
                    }
                }
                // Back substitution
                y[NC - 1] *= invd[NC - 1];
#pragma unroll
                for (int a = NC - 2; a >= 0; --a) {
                    float s = y[a];
#pragma unroll
                    for (int k = a + 1; k < NC; ++k)
                        s = fmaf(-Lm[k][a], y[k], s);
                    y[a] = s * invd[a];
                }
                if (tid < NS) {
#pragma unroll
                    for (int a = 0; a < NC; ++a) { sK[a][tid] = y[a]; g_K[t][a][tid] = y[a]; }
                } else {
#pragma unroll
                    for (int a = 0; a < NC; ++a) { skk[a] = y[a]; g_kk[t][a] = y[a]; }
                }
            }
        } else if (tid < 128) {
            // Qxx rows
            float4 s = cregA;
            if (notlast) {
#pragma unroll
                for (int k = 0; k < NS; ++k) {
                    float f = sF[k][xi];                    // broadcast LDS
                    float4 w = *(const float4*)&sW[k][4 * xjq];
                    s.x = fmaf(f, w.x, s.x); s.y = fmaf(f, w.y, s.y);
                    s.z = fmaf(f, w.z, s.z); s.w = fmaf(f, w.w, s.w);
                }
            }
            *(float4*)&sQ[xi][4 * xjq] = s;
            if (t > 0) cregA = C4[(t - 1) * 144 + xi * 6 + xjq];
        } else if (tid < 144) {
            // qx
            int i = tid - 128;
            float s = scq[par][i];
            if (notlast) {
#pragma unroll
                for (int k = 0; k < NS; ++k) s = fmaf(sF[k][i], sp[k], s);
            }
            sq[i] = s;
        } else if (tid < 150) {
            // stage c prefetch for t-1
            if (t > 0)
                ((float4*)scq[1 - par])[tid - 144] =
                    ((const float4*)(c + (t - 1) * NA))[tid - 144];
        }
        __syncthreads();

        // ---- P3: P, p, Acl, bias ----
        if (tid < 64) {                 // P = Qxx - Qxu K
            int i = tid & 15, jq = tid >> 4;
            float4 s = *(const float4*)&sQ[i][4 * jq];
#pragma unroll
            for (int m = 0; m < NC; ++m) {
                float qm = sQ[i][NS + m];
                float4 kv = *(const float4*)&sK[m][4 * jq];
                s.x = fmaf(-qm, kv.x, s.x); s.y = fmaf(-qm, kv.y, s.y);
                s.z = fmaf(-qm, kv.z, s.z); s.w = fmaf(-qm, kv.w, s.w);
            }
            *(float4*)&sP[i][4 * jq] = s;
            *(float4*)&g_P[t][i][4 * jq] = s;
        } else if (tid < 80) {          // p = qx - Qxu kk
            int i = tid - 64;
            float s = sq[i];
#pragma unroll
            for (int m = 0; m < NC; ++m) s = fmaf(-sQ[i][NS + m], skk[m], s);
            sp[i] = s; g_p[t][i] = s;
        } else if (tid < 144) {         // Acl = A - B K
            int idx = tid - 80, i = idx & 15, jq = idx >> 4;
            float4 s = *(const float4*)&sF[i][4 * jq];
#pragma unroll
            for (int m = 0; m < NC; ++m) {
                float bm2 = sF[i][NS + m];
                float4 kv = *(const float4*)&sK[m][4 * jq];
                s.x = fmaf(-bm2, kv.x, s.x); s.y = fmaf(-bm2, kv.y, s.y);
                s.z = fmaf(-bm2, kv.z, s.z); s.w = fmaf(-bm2, kv.w, s.w);
            }
            float* ap = &sAcl[(t * NS + i) * AS + 4 * jq];
            ap[0] = s.x; ap[1] = s.y; ap[2] = s.z; ap[3] = s.w;
        } else {                        // bias = -B kk
            int i = tid - 144;
            float s = 0.f;
#pragma unroll
            for (int m = 0; m < NC; ++m) s = fmaf(-sF[i][NS + m], skk[m], s);
            sBias[t][i] = s;
        }
        __syncthreads();

        // ---- P4: W = P * F ----
        if (tid < 96) {
            int i = tid & 15, jq = tid >> 4;
            float4 s = make_float4(0.f, 0.f, 0.f, 0.f);
#pragma unroll
            for (int k = 0; k < NS; ++k) {
                float p = sP[i][k];
                float4 f = *(const float4*)&sF[k][4 * jq];
                s.x = fmaf(p, f.x, s.x); s.y = fmaf(p, f.y, s.y);
                s.z = fmaf(p, f.z, s.z); s.w = fmaf(p, f.w, s.w);
            }
            *(float4*)&sW[i][4 * jq] = s;
        }
        __syncthreads();
    }

    // ---------------- Forward rollout: single warp, shuffle recurrence ----------------
    if (tid < 32) {
        int i = tid & 15;
        float x = (tid < NS) ? x0[tid] : 0.f;
#pragma unroll 1
        for (int t = 0; t < TT; ++t) {
            if (tid < NS) { out[t * NA + tid] = x; sX[t][tid] = x; }
            if (t < TT - 1) {
                float s = sBias[t][i];
                const float* ar = &sAcl[(t * NS + i) * AS];
#pragma unroll
                for (int k = 0; k < NS; ++k) {
                    float xk = __shfl_sync(0xffffffffu, x, k);
                    s = fmaf(ar[k], xk, s);
                }
                x = s;
            }
        }
    }
    __syncthreads();

    // ---------------- Parallel output post-pass ----------------
    for (int idx = tid; idx < TT * NC; idx += NTHR) {
        int t = idx >> 3, m = idx & 7;
        float s = g_kk[t][m];
        const float4* Kr = (const float4*)&g_K[t][m][0];
        const float* xr = &sX[t][0];
#pragma unroll
        for (int q = 0; q < 4; ++q) {
            float4 v = Kr[q];
            s = fmaf(v.x, xr[4 * q + 0], s); s = fmaf(v.y, xr[4 * q + 1], s);
            s = fmaf(v.z, xr[4 * q + 2], s); s = fmaf(v.w, xr[4 * q + 3], s);
        }
        out[t * NA + NS + m] = -s;
    }
    for (int idx = tid; idx < TT * NS; idx += NTHR) {
        int t = idx >> 4, i = idx & 15;
        float s = g_p[t][i];
        const float4* Pr = (const float4*)&g_P[t][i][0];
        const float* xr = &sX[t][0];
#pragma unroll
        for (int q = 0; q < 4; ++q) {
            float4 v = Pr[q];
            s = fmaf(v.x, xr[4 * q + 0], s); s = fmaf(v.y, xr[4 * q + 1], s);
            s = fmaf(v.z, xr[4 * q + 2], s); s = fmaf(v.w, xr[4 * q + 3], s);
        }
        out[TT * NA + idx] = (t == 0) ? -s : s;
    }
}

extern "C" void kernel_launch(void* const* d_in, const int* in_sizes, int n_in,
                              void* d_out, int out_size) {
    const float* A  = (const float*)d_in[0];
    const float* B  = (const float*)d_in[1];
    const float* x0 = (const float*)d_in[2];
    const float* C  = (const float*)d_in[3];
    const float* c  = (const float*)d_in[4];
    float* out = (float*)d_out;

    const int dyn = TT * NS * AS * sizeof(float);  // 139264 B
    cudaFuncSetAttribute(lqr_kernel, cudaFuncAttributeMaxDynamicSharedMemorySize, dyn);
    lqr_kernel<<<1, NTHR, dyn>>>(A, B, x0, C, c, out);
}

// round 6
// speedup vs baseline: 1.2802x; 1.2802x over previous
#include <cuda_runtime.h>

// LQR via Riccati recursion. T=128, n_state=16, n_ctrl=8, n_all=24.
// Single CTA, 160 threads. Stage (4 barriers):
//  Ph1: Q = C + F^T W (144 f4 tasks, register-cached F) ; q = c + F^T p
//  Ph2: warp0: fused Cholesky+solves (K,kk)  ||  warps1-4: X = Qxx*F and
//       DEFERRED outputs of stage t+1: P, Acl, bias (double-buffered Q,K)
//  Ph3: KF = K*F ; p = qx - Qxu kk
//  Ph4: W = X - Qxu*KF      (== P*F, reassociated)
// After loop: flush deferred outputs for t=0. Then rollout + output post-pass.

constexpr int TT = 128, NS = 16, NC = 8, NA = 24;
constexpr int NTHR = 160;
constexpr int CST4 = NA * NA / 4;   // 144 float4 per stage of C

constexpr int QS = 28;   // sQ row stride (floats)
constexpr int WS = 28;   // sW / sXF row stride
constexpr int KFS = 28;  // sKF row stride
constexpr int AS = 17;   // Acl row stride

__device__ __align__(16) float g_K[TT][NC][NS];
__device__ float g_kk[TT][NC];
__device__ __align__(16) float g_P[TT][NS][NS];
__device__ float g_p[TT][NS];

__global__ void __launch_bounds__(NTHR, 1) lqr_kernel(
    const float* __restrict__ A, const float* __restrict__ B,
    const float* __restrict__ x0, const float* __restrict__ C,
    const float* __restrict__ c, float* __restrict__ out)
{
    extern __shared__ float sAcl[];              // [TT][NS][AS]
    __shared__ __align__(16) float sF[NS][NA];   // [A B]
    __shared__ __align__(16) float sW[NS][WS];   // recursion state
    __shared__ __align__(16) float sQ[2][NA][QS];// double-buffered Q
    __shared__ __align__(16) float sXF[NS][WS];  // X = Qxx*F
    __shared__ __align__(16) float sKF[NC][KFS]; // K*F
    __shared__ __align__(16) float sK[2][NC][NS];
    __shared__ float skk[2][NC];
    __shared__ float sq[NA], sp[NS];
    __shared__ __align__(16) float scq[2][NA];
    __shared__ float sBias[TT][NS];
    __shared__ float sXs[TT][NS];

    const int tid = threadIdx.x;

    for (int idx = tid; idx < NS * NA; idx += NTHR) {
        int i = idx / NA, j = idx % NA;
        sF[i][j] = (j < NS) ? A[i * NS + j] : B[i * NC + (j - NS)];
    }
    if (tid < NA) scq[(TT - 1) & 1][tid] = c[(TT - 1) * NA + tid];
    __syncthreads();

    const float4* C4 = (const float4*)C;

    // Ph1 mapping (as R2): tid<144 -> Q element row ci, col-quad jqB.
    const int ci  = tid % NA;
    const int jqB = tid / NA;
    float Fc[NS];
#pragma unroll
    for (int k = 0; k < NS; ++k) Fc[k] = sF[k][ci];

    float4 creg = make_float4(0.f, 0.f, 0.f, 0.f);
    float  cq   = 0.f;
    if (tid < 144) creg = C4[(TT - 1) * CST4 + ci * 6 + jqB];
    if (tid < NA)  cq   = c[(TT - 1) * NA + tid];   // redundant w/ scq but cheap

    // ---------------- Backward Riccati pass ----------------
#pragma unroll 1
    for (int t = TT - 1; t >= 0; --t) {
        const int par = t & 1, pp = par ^ 1;
        const bool notlast = (t != TT - 1);

        // ---- Ph1: Q = C + F^T W ; q = c + F^T p ----
        if (tid < 144) {
            float4 s = creg;
            if (notlast) {
#pragma unroll
                for (int k = 0; k < NS; ++k) {
                    float f = Fc[k];
                    float4 w = *(const float4*)&sW[k][4 * jqB];
                    s.x = fmaf(f, w.x, s.x); s.y = fmaf(f, w.y, s.y);
                    s.z = fmaf(f, w.z, s.z); s.w = fmaf(f, w.w, s.w);
                }
            }
            *(float4*)&sQ[par][ci][4 * jqB] = s;
            if (t > 0) creg = C4[(t - 1) * CST4 + ci * 6 + jqB];
        } else if (tid < 150) {
            // stage c_{t-1} into other parity buffer
            if (t > 0)
                ((float4*)scq[1 - par])[tid - 144] =
                    ((const float4*)(c + (t - 1) * NA))[tid - 144];
        }
        if (tid < NA) {
            float s = scq[par][tid];
            if (notlast) {
#pragma unroll
                for (int k = 0; k < NS; ++k) s = fmaf(Fc[k], sp[k], s);
            }
            sq[tid] = s;
        }
        __syncthreads();

        // ---- Ph2: CD (warp0) || X, deferred P/Acl/bias (warps 1-4) ----
        if (tid < 32) {
            if (tid <= NS) {
                // fused right-looking Cholesky + forward solve (register-resident)
                float Lm[NC][NC], invd[NC], y[NC];
#pragma unroll
                for (int j = 0; j < NC; ++j)
#pragma unroll
                    for (int i = 0; i < NC; ++i)
                        if (i >= j) Lm[i][j] = sQ[par][NS + i][NS + j];
#pragma unroll
                for (int a = 0; a < NC; ++a)
                    y[a] = (tid < NS) ? sQ[par][NS + a][tid] : sq[NS + a];
#pragma unroll
                for (int j = 0; j < NC; ++j) {
                    float r = rsqrtf(Lm[j][j]);
                    invd[j] = r;
                    y[j] *= r;
#pragma unroll
                    for (int i = j + 1; i < NC; ++i) Lm[i][j] *= r;
#pragma unroll
                    for (int i = j + 1; i < NC; ++i) {
                        y[i] = fmaf(-Lm[i][j], y[j], y[i]);
#pragma unroll
                        for (int l = j + 1; l <= i; ++l)
                            Lm[i][l] = fmaf(-Lm[i][j], Lm[l][j], Lm[i][l]);
                    }
                }
                y[NC - 1] *= invd[NC - 1];
#pragma unroll
                for (int a = NC - 2; a >= 0; --a) {
                    float s = y[a];
#pragma unroll
                    for (int k = a + 1; k < NC; ++k) s = fmaf(-Lm[k][a], y[k], s);
                    y[a] = s * invd[a];
                }
                if (tid < NS) {
#pragma unroll
                    for (int a = 0; a < NC; ++a) { sK[par][a][tid] = y[a]; g_K[t][a][tid] = y[a]; }
                } else {
#pragma unroll
                    for (int a = 0; a < NC; ++a) { skk[par][a] = y[a]; g_kk[t][a] = y[a]; }
                }
            }
        } else {
            const int tau = tid - 32;   // 0..127; two task slots: tau, tau+128
#pragma unroll
            for (int slot = 0; slot < 2; ++slot) {
                int tk = tau + slot * 128;
                if (tk < 96) {
                    // X = Qxx * F   (i = tk/6, jq = tk%6)
                    int i = tk / 6, jq = tk % 6;
                    float4 s = make_float4(0.f, 0.f, 0.f, 0.f);
#pragma unroll
                    for (int k = 0; k < NS; ++k) {
                        float qv = sQ[par][i][k];
                        float4 f = *(const float4*)&sF[k][4 * jq];
                        s.x = fmaf(qv, f.x, s.x); s.y = fmaf(qv, f.y, s.y);
                        s.z = fmaf(qv, f.z, s.z); s.w = fmaf(qv, f.w, s.w);
                    }
                    *(float4*)&sXF[i][4 * jq] = s;
                } else if (tk < 160) {
                    // deferred P_{t+1} = Qxx - Qxu K  -> g_P[t+1]
                    if (notlast) {
                        int idx = tk - 96, i = idx >> 2, jq = idx & 3;
                        float4 s = *(const float4*)&sQ[pp][i][4 * jq];
#pragma unroll
                        for (int m = 0; m < NC; ++m) {
                            float qm = sQ[pp][i][NS + m];
                            float4 kv = *(const float4*)&sK[pp][m][4 * jq];
                            s.x = fmaf(-qm, kv.x, s.x); s.y = fmaf(-qm, kv.y, s.y);
                            s.z = fmaf(-qm, kv.z, s.z); s.w = fmaf(-qm, kv.w, s.w);
                        }
                        *(float4*)&g_P[t + 1][i][4 * jq] = s;
                    }
                } else if (tk < 224) {
                    // deferred Acl_{t+1} = A - B K
                    if (notlast) {
                        int idx = tk - 160, i = idx >> 2, jq = idx & 3;
                        float4 s = *(const float4*)&sF[i][4 * jq];
#pragma unroll
                        for (int m = 0; m < NC; ++m) {
                            float bm = sF[i][NS + m];
                            float4 kv = *(const float4*)&sK[pp][m][4 * jq];
                            s.x = fmaf(-bm, kv.x, s.x); s.y = fmaf(-bm, kv.y, s.y);
                            s.z = fmaf(-bm, kv.z, s.z); s.w = fmaf(-bm, kv.w, s.w);
                        }
                        float* ap = &sAcl[((t + 1) * NS + i) * AS + 4 * jq];
                        ap[0] = s.x; ap[1] = s.y; ap[2] = s.z; ap[3] = s.w;
                    }
                } else if (tk < 240) {
                    // deferred bias_{t+1} = -B kk
                    if (notlast) {
                        int i = tk - 224;
                        float s = 0.f;
#pragma unroll
                        for (int m = 0; m < NC; ++m) s = fmaf(-sF[i][NS + m], skk[pp][m], s);
                        sBias[t + 1][i] = s;
                    }
                }
            }
        }
        __syncthreads();

        // ---- Ph3: KF = K*F ; p = qx - Qxu kk ----
        if (tid < 48) {
            int m = tid / 6, jq = tid % 6;
            float4 s = make_float4(0.f, 0.f, 0.f, 0.f);
#pragma unroll
            for (int k = 0; k < NS; ++k) {
                float kv = sK[par][m][k];
                float4 f = *(const float4*)&sF[k][4 * jq];
                s.x = fmaf(kv, f.x, s.x); s.y = fmaf(kv, f.y, s.y);
                s.z = fmaf(kv, f.z, s.z); s.w = fmaf(kv, f.w, s.w);
            }
            *(float4*)&sKF[m][4 * jq] = s;
        } else if (tid < 64) {
            int i = tid - 48;
            float s = sq[i];
#pragma unroll
            for (int m = 0; m < NC; ++m) s = fmaf(-sQ[par][i][NS + m], skk[par][m], s);
            sp[i] = s; g_p[t][i] = s;
        }
        __syncthreads();

        // ---- Ph4: W = X - Qxu * KF ----
        if (tid < 96) {
            int i = tid / 6, jq = tid % 6;
            float4 s = *(const float4*)&sXF[i][4 * jq];
#pragma unroll
            for (int m = 0; m < NC; ++m) {
                float qm = sQ[par][i][NS + m];
                float4 kf = *(const float4*)&sKF[m][4 * jq];
                s.x = fmaf(-qm, kf.x, s.x); s.y = fmaf(-qm, kf.y, s.y);
                s.z = fmaf(-qm, kf.z, s.z); s.w = fmaf(-qm, kf.w, s.w);
            }
            *(float4*)&sW[i][4 * jq] = s;
        }
        __syncthreads();
    }

    // ---- flush deferred outputs for t = 0 (par = 0) ----
    if (tid < 64) {                       // P_0 -> g_P[0]
        int i = tid >> 2, jq = tid & 3;
        float4 s = *(const float4*)&sQ[0][i][4 * jq];
#pragma unroll
        for (int m = 0; m < NC; ++m) {
            float qm = sQ[0][i][NS + m];
            float4 kv = *(const float4*)&sK[0][m][4 * jq];
            s.x = fmaf(-qm, kv.x, s.x); s.y = fmaf(-qm, kv.y, s.y);
            s.z = fmaf(-qm, kv.z, s.z); s.w = fmaf(-qm, kv.w, s.w);
        }
        *(float4*)&g_P[0][i][4 * jq] = s;
    } else if (tid < 128) {               // Acl_0
        int idx = tid - 64, i = idx >> 2, jq = idx & 3;
        float4 s = *(const float4*)&sF[i][4 * jq];
#pragma unroll
        for (int m = 0; m < NC; ++m) {
            float bm = sF[i][NS + m];
            float4 kv = *(const float4*)&sK[0][m][4 * jq];
            s.x = fmaf(-bm, kv.x, s.x); s.y = fmaf(-bm, kv.y, s.y);
            s.z = fmaf(-bm, kv.z, s.z); s.w = fmaf(-bm, kv.w, s.w);
        }
        float* ap = &sAcl[(0 * NS + i) * AS + 4 * jq];
        ap[0] = s.x; ap[1] = s.y; ap[2] = s.z; ap[3] = s.w;
    } else if (tid < 144) {               // bias_0
        int i = tid - 128;
        float s = 0.f;
#pragma unroll
        for (int m = 0; m < NC; ++m) s = fmaf(-sF[i][NS + m], skk[0][m], s);
        sBias[0][i] = s;
    }
    __syncthreads();

    // ---------------- Forward rollout: single warp, shuffle recurrence ----------------
    if (tid < 32) {
        int i = tid & 15;
        float x = (tid < NS) ? x0[tid] : 0.f;
#pragma unroll 1
        for (int t = 0; t < TT; ++t) {
            if (tid < NS) { out[t * NA + tid] = x; sXs[t][tid] = x; }
            if (t < TT - 1) {
                float s = sBias[t][i];
                const float* ar = &sAcl[(t * NS + i) * AS];
#pragma unroll
                for (int k = 0; k < NS; ++k) {
                    float xk = __shfl_sync(0xffffffffu, x, k);
                    s = fmaf(ar[k], xk, s);
                }
                x = s;
            }
        }
    }
    __syncthreads();

    // ---------------- Parallel output post-pass ----------------
    for (int idx = tid; idx < TT * NC; idx += NTHR) {
        int t = idx >> 3, m = idx & 7;
        float s = g_kk[t][m];
        const float4* Kr = (const float4*)&g_K[t][m][0];
        const float* xr = &sXs[t][0];
#pragma unroll
        for (int q = 0; q < 4; ++q) {
            float4 v = Kr[q];
            s = fmaf(v.x, xr[4 * q + 0], s); s = fmaf(v.y, xr[4 * q + 1], s);
            s = fmaf(v.z, xr[4 * q + 2], s); s = fmaf(v.w, xr[4 * q + 3], s);
        }
        out[t * NA + NS + m] = -s;
    }
    for (int idx = tid; idx < TT * NS; idx += NTHR) {
        int t = idx >> 4, i = idx & 15;
        float s = g_p[t][i];
        const float4* Pr = (const float4*)&g_P[t][i][0];
        const float* xr = &sXs[t][0];
#pragma unroll
        for (int q = 0; q < 4; ++q) {
            float4 v = Pr[q];
            s = fmaf(v.x, xr[4 * q + 0], s); s = fmaf(v.y, xr[4 * q + 1], s);
            s = fmaf(v.z, xr[4 * q + 2], s); s = fmaf(v.w, xr[4 * q + 3], s);
        }
        out[TT * NA + idx] = (t == 0) ? -s : s;
    }
}

extern "C" void kernel_launch(void* const* d_in, const int* in_sizes, int n_in,
                              void* d_out, int out_size) {
    const float* A  = (const float*)d_in[0];
    const float* B  = (const float*)d_in[1];
    const float* x0 = (const float*)d_in[2];
    const float* C  = (const float*)d_in[3];
    const float* c  = (const float*)d_in[4];
    float* out = (float*)d_out;

    const int dyn = TT * NS * AS * sizeof(float);  // 139264 B
    cudaFuncSetAttribute(lqr_kernel, cudaFuncAttributeMaxDynamicSharedMemorySize, dyn);
    lqr_kernel<<<1, NTHR, dyn>>>(A, B, x0, C, c, out);
}

// round 7
// speedup vs baseline: 1.4524x; 1.1345x over previous
#include <cuda_runtime.h>

// LQR via Riccati recursion. T=128, n_state=16, n_ctrl=8, n_all=24.
// Single CTA, 160 threads. R2 structure (proven fastest) + fused CD + LDS.128 micro-opts.

constexpr int TT = 128, NS = 16, NC = 8, NA = 24;
constexpr int NTHR = 160;
constexpr int CST4 = NA * NA / 4;  // 144 float4 per stage of C

constexpr int QS = 28;  // sQ row stride (floats)
constexpr int WS = 28;  // sW row stride
constexpr int PS = 20;  // sP row stride
constexpr int AS = 17;  // Acl row stride

__device__ __align__(16) float g_K[TT][NC][NS];
__device__ float g_kk[TT][NC];
__device__ __align__(16) float g_P[TT][NS][NS];
__device__ float g_p[TT][NS];

__global__ void __launch_bounds__(NTHR, 1) lqr_kernel(
    const float* __restrict__ A, const float* __restrict__ B,
    const float* __restrict__ x0, const float* __restrict__ C,
    const float* __restrict__ c, float* __restrict__ out)
{
    extern __shared__ float sAcl[];            // [TT][NS][AS]
    __shared__ __align__(16) float sF[NS][NA]; // [A B]
    __shared__ __align__(16) float sW[NS][WS];
    __shared__ __align__(16) float sQ[NA][QS];
    __shared__ __align__(16) float sP[NS][PS];
    __shared__ __align__(16) float sK[NC][NS];
    __shared__ float sq[NA], sp[NS], skk[NC];
    __shared__ float sBias[TT][NS];
    __shared__ float sX[TT][NS];

    const int tid = threadIdx.x;

    for (int idx = tid; idx < NS * NA; idx += NTHR) {
        int i = idx / NA, j = idx % NA;
        sF[i][j] = (j < NS) ? A[i * NS + j] : B[i * NC + (j - NS)];
    }
    __syncthreads();

    // Phase-B mapping: tid<144 -> row ci, column-quad jqB; F column cached in regs
    const int ci  = tid % NA;
    const int jqB = tid / NA;
    float Fc[NS];
#pragma unroll
    for (int k = 0; k < NS; ++k) Fc[k] = sF[k][ci];

    const float4* C4 = (const float4*)C;
    float4 creg = make_float4(0.f, 0.f, 0.f, 0.f);
    float  cq   = 0.f;
    if (tid < 144) creg = C4[(TT - 1) * CST4 + ci * 6 + jqB];
    if (tid < NA)  cq   = c[(TT - 1) * NA + tid];

    // ---------------- Backward Riccati pass ----------------
#pragma unroll 1
    for (int t = TT - 1; t >= 0; --t) {
        const bool notlast = (t != TT - 1);

        if (notlast) {
            // Phase A: W = P * F (96 threads, 1x4 strips; P loaded as float4)
            if (tid < 96) {
                int i = tid & 15, jq = tid >> 4;
                float4 s = make_float4(0.f, 0.f, 0.f, 0.f);
#pragma unroll
                for (int kq = 0; kq < 4; ++kq) {
                    float4 p4 = *(const float4*)&sP[i][4 * kq];
#pragma unroll
                    for (int kk2 = 0; kk2 < 4; ++kk2) {
                        float p = (kk2 == 0) ? p4.x : (kk2 == 1) ? p4.y : (kk2 == 2) ? p4.z : p4.w;
                        float4 f = *(const float4*)&sF[4 * kq + kk2][4 * jq];
                        s.x = fmaf(p, f.x, s.x); s.y = fmaf(p, f.y, s.y);
                        s.z = fmaf(p, f.z, s.z); s.w = fmaf(p, f.w, s.w);
                    }
                }
                *(float4*)&sW[i][4 * jq] = s;
            }
            __syncthreads();
        }

        // Phase B: Q = C_t + F^T W ; q = c_t + F^T p
        if (tid < 144) {
            float4 s = creg;
            if (notlast) {
#pragma unroll
                for (int k = 0; k < NS; ++k) {
                    float f = Fc[k];
                    float4 w = *(const float4*)&sW[k][4 * jqB];
                    s.x = fmaf(f, w.x, s.x); s.y = fmaf(f, w.y, s.y);
                    s.z = fmaf(f, w.z, s.z); s.w = fmaf(f, w.w, s.w);
                }
            }
            *(float4*)&sQ[ci][4 * jqB] = s;
        }
        if (tid < NA) {
            float s = cq;
            if (notlast) {
#pragma unroll
                for (int k = 0; k < NS; ++k) s = fmaf(Fc[k], sp[k], s);
            }
            sq[tid] = s;
        }
        // Prefetch next stage's cost tile (hidden behind CD)
        if (t > 0) {
            if (tid < 144) creg = C4[(t - 1) * CST4 + ci * 6 + jqB];
            if (tid < NA)  cq   = c[(t - 1) * NA + tid];
        }
        __syncthreads();

        // Phase C+D: lanes 0..16, fused right-looking Cholesky + forward solve
        // (register-resident, redundant per-lane; rsqrtf, no divides)
        if (tid <= NS) {
            float Lm[NC][NC], invd[NC], y[NC];
#pragma unroll
            for (int j = 0; j < NC; ++j)
#pragma unroll
                for (int i = 0; i < NC; ++i)
                    if (i >= j) Lm[i][j] = sQ[NS + i][NS + j];
#pragma unroll
            for (int a = 0; a < NC; ++a)
                y[a] = (tid < NS) ? sQ[NS + a][tid] : sq[NS + a];
#pragma unroll
            for (int j = 0; j < NC; ++j) {
                float r = rsqrtf(Lm[j][j]);
                invd[j] = r;
                y[j] *= r;
#pragma unroll
                for (int i = j + 1; i < NC; ++i) Lm[i][j] *= r;
#pragma unroll
                for (int i = j + 1; i < NC; ++i) {
                    y[i] = fmaf(-Lm[i][j], y[j], y[i]);
#pragma unroll
                    for (int l = j + 1; l <= i; ++l)
                        Lm[i][l] = fmaf(-Lm[i][j], Lm[l][j], Lm[i][l]);
                }
            }
            y[NC - 1] *= invd[NC - 1];
#pragma unroll
            for (int a = NC - 2; a >= 0; --a) {
                float s = y[a];
#pragma unroll
                for (int k = a + 1; k < NC; ++k) s = fmaf(-Lm[k][a], y[k], s);
                y[a] = s * invd[a];
            }
            if (tid < NS) {
#pragma unroll
                for (int a = 0; a < NC; ++a) { sK[a][tid] = y[a]; g_K[t][a][tid] = y[a]; }
            } else {
#pragma unroll
                for (int a = 0; a < NC; ++a) { skk[a] = y[a]; g_kk[t][a] = y[a]; }
            }
        }
        __syncthreads();

        // Phase E: P, p, Acl, bias (160 threads, Qxu/B rows loaded as float4)
        if (tid < 64) {                 // P = Qxx - Qxu K
            int i = tid & 15, jq = tid >> 4;
            float4 s = *(const float4*)&sQ[i][4 * jq];
            float4 q0 = *(const float4*)&sQ[i][NS];
            float4 q1 = *(const float4*)&sQ[i][NS + 4];
#pragma unroll
            for (int m = 0; m < NC; ++m) {
                float qm = (m == 0) ? q0.x : (m == 1) ? q0.y : (m == 2) ? q0.z : (m == 3) ? q0.w
                         : (m == 4) ? q1.x : (m == 5) ? q1.y : (m == 6) ? q1.z : q1.w;
                float4 kv = *(const float4*)&sK[m][4 * jq];
                s.x = fmaf(-qm, kv.x, s.x); s.y = fmaf(-qm, kv.y, s.y);
                s.z = fmaf(-qm, kv.z, s.z); s.w = fmaf(-qm, kv.w, s.w);
            }
            *(float4*)&sP[i][4 * jq] = s;
            *(float4*)&g_P[t][i][4 * jq] = s;
        } else if (tid < 80) {          // p = qx - Qxu kk
            int i = tid - 64;
            float4 q0 = *(const float4*)&sQ[i][NS];
            float4 q1 = *(const float4*)&sQ[i][NS + 4];
            float s = sq[i];
            s = fmaf(-q0.x, skk[0], s); s = fmaf(-q0.y, skk[1], s);
            s = fmaf(-q0.z, skk[2], s); s = fmaf(-q0.w, skk[3], s);
            s = fmaf(-q1.x, skk[4], s); s = fmaf(-q1.y, skk[5], s);
            s = fmaf(-q1.z, skk[6], s); s = fmaf(-q1.w, skk[7], s);
            sp[i] = s; g_p[t][i] = s;
        } else if (tid < 144) {         // Acl = A - B K
            int idx = tid - 80, i = idx & 15, jq = idx >> 4;
            float4 s = *(const float4*)&sF[i][4 * jq];
            float4 b0 = *(const float4*)&sF[i][NS];
            float4 b1 = *(const float4*)&sF[i][NS + 4];
#pragma unroll
            for (int m = 0; m < NC; ++m) {
                float bm = (m == 0) ? b0.x : (m == 1) ? b0.y : (m == 2) ? b0.z : (m == 3) ? b0.w
                         : (m == 4) ? b1.x : (m == 5) ? b1.y : (m == 6) ? b1.z : b1.w;
                float4 kv = *(const float4*)&sK[m][4 * jq];
                s.x = fmaf(-bm, kv.x, s.x); s.y = fmaf(-bm, kv.y, s.y);
                s.z = fmaf(-bm, kv.z, s.z); s.w = fmaf(-bm, kv.w, s.w);
            }
            float* ap = &sAcl[(t * NS + i) * AS + 4 * jq];
            ap[0] = s.x; ap[1] = s.y; ap[2] = s.z; ap[3] = s.w;
        } else {                        // bias = -B kk
            int i = tid - 144;
            float4 b0 = *(const float4*)&sF[i][NS];
            float4 b1 = *(const float4*)&sF[i][NS + 4];
            float s = 0.f;
            s = fmaf(-b0.x, skk[0], s); s = fmaf(-b0.y, skk[1], s);
            s = fmaf(-b0.z, skk[2], s); s = fmaf(-b0.w, skk[3], s);
            s = fmaf(-b1.x, skk[4], s); s = fmaf(-b1.y, skk[5], s);
            s = fmaf(-b1.z, skk[6], s); s = fmaf(-b1.w, skk[7], s);
            sBias[t][i] = s;
        }
        __syncthreads();
    }

    // ---------------- Forward rollout: single warp, shuffle recurrence ----------------
    if (tid < 32) {
        int i = tid & 15;
        float x = (tid < NS) ? x0[tid] : 0.f;
#pragma unroll 1
        for (int t = 0; t < TT; ++t) {
            if (tid < NS) { out[t * NA + tid] = x; sX[t][tid] = x; }
            if (t < TT - 1) {
                float s = sBias[t][i];
                const float* ar = &sAcl[(t * NS + i) * AS];
#pragma unroll
                for (int k = 0; k < NS; ++k) {
                    float xk = __shfl_sync(0xffffffffu, x, k);
                    s = fmaf(ar[k], xk, s);
                }
                x = s;
            }
        }
    }
    __syncthreads();

    // ---------------- Parallel output post-pass ----------------
    for (int idx = tid; idx < TT * NC; idx += NTHR) {
        int t = idx >> 3, m = idx & 7;
        float s = g_kk[t][m];
        const float4* Kr = (const float4*)&g_K[t][m][0];
        const float* xr = &sX[t][0];
#pragma unroll
        for (int q = 0; q < 4; ++q) {
            float4 v = Kr[q];
            s = fmaf(v.x, xr[4 * q + 0], s); s = fmaf(v.y, xr[4 * q + 1], s);
            s = fmaf(v.z, xr[4 * q + 2], s); s = fmaf(v.w, xr[4 * q + 3], s);
        }
        out[t * NA + NS + m] = -s;
    }
    for (int idx = tid; idx < TT * NS; idx += NTHR) {
        int t = idx >> 4, i = idx & 15;
        float s = g_p[t][i];
        const float4* Pr = (const float4*)&g_P[t][i][0];
        const float* xr = &sX[t][0];
#pragma unroll
        for (int q = 0; q < 4; ++q) {
            float4 v = Pr[q];
            s = fmaf(v.x, xr[4 * q + 0], s); s = fmaf(v.y, xr[4 * q + 1], s);
            s = fmaf(v.z, xr[4 * q + 2], s); s = fmaf(v.w, xr[4 * q + 3], s);
        }
        out[TT * NA + idx] = (t == 0) ? -s : s;
    }
}

extern "C" void kernel_launch(void* const* d_in, const int* in_sizes, int n_in,
                              void* d_out, int out_size) {
    const float* A  = (const float*)d_in[0];
    const float* B  = (const float*)d_in[1];
    const float* x0 = (const float*)d_in[2];
    const float* C  = (const float*)d_in[3];
    const float* c  = (const float*)d_in[4];
    float* out = (float*)d_out;

    const int dyn = TT * NS * AS * sizeof(float);  // 139264 B
    cudaFuncSetAttribute(lqr_kernel, cudaFuncAttributeMaxDynamicSharedMemorySize, dyn);
    lqr_kernel<<<1, NTHR, dyn>>>(A, B, x0, C, c, out);
}